// round 1
// baseline (speedup 1.0000x reference)
#include <cuda_runtime.h>
#include <math.h>

#define D_MODEL 512
#define HEADS   8
#define HD      64
#define SEQ     2048
#define BATCH   4
#define MTOT    (BATCH*SEQ)   /* 8192 */

// ---------------- scratch (static device allocations; no cudaMalloc) --------
__device__ float g_qkv[3][MTOT*D_MODEL];    // q,k,v after first GEMM (+RoPE in place)
__device__ float g_heads[3][MTOT*D_MODEL];  // qp,kp,vp in [B,H,S,HD]
__device__ float g_attn[MTOT*D_MODEL];      // attention output in [B,S,D]
__device__ float g_tab[SEQ*(D_MODEL/2)*2];  // (cos,sin) per (pos, pair)

// ---------------- RoPE table: gather cos/sin from the dense R input ---------
__global__ void rope_table_kernel(const float* __restrict__ R, float* __restrict__ tab) {
    int i = threadIdx.x;              // pair index 0..255
    int m = blockIdx.x;               // position  0..2047
    const float* Rm = R + (size_t)m * D_MODEL * D_MODEL;
    float c = Rm[(size_t)(2*i)   * D_MODEL + 2*i];   // cos
    float s = Rm[(size_t)(2*i+1) * D_MODEL + 2*i];   // sin
    ((float2*)tab)[m*(D_MODEL/2) + i] = make_float2(c, s);
}

// ---------------- RoPE apply (in place on q,k,v stacked buffer) -------------
// q'[2i]   =  q[2i]*cos + q[2i+1]*sin
// q'[2i+1] = -q[2i]*sin + q[2i+1]*cos
__global__ void rope_apply_kernel(float* __restrict__ x, const float* __restrict__ tab) {
    int row = blockIdx.x;             // 0 .. 3*MTOT-1
    int i   = threadIdx.x;            // 0..255
    int m   = row & (SEQ - 1);        // seq position
    float2 cs = ((const float2*)tab)[m*(D_MODEL/2) + i];
    float2* xp = (float2*)x;
    float2 v = xp[(size_t)row*(D_MODEL/2) + i];
    float2 o;
    o.x =  v.x*cs.x + v.y*cs.y;
    o.y = -v.x*cs.y + v.y*cs.x;
    xp[(size_t)row*(D_MODEL/2) + i] = o;
}

// ---------------- SGEMM: C = A[M,K] @ B[N,K]^T (+bias), optional head-permute
// PERM==0: C[m][n].  PERM==1: C -> [B,H,S,HD] layout (n = h*HD+c, m = b*SEQ+s)
template<int PERM>
__global__ void __launch_bounds__(256) sgemm_nt(
    const float* __restrict__ A, const float* __restrict__ B,
    const float* __restrict__ bias, float* __restrict__ C,
    int M, int N, int K)
{
    const int BK = 16;
    __shared__ float As[BK][68];
    __shared__ float Bs[BK][68];
    int tid = threadIdx.x;
    int tx = tid & 15, ty = tid >> 4;
    int m0 = blockIdx.y * 64, n0 = blockIdx.x * 64;

    float acc[4][4] = {};

    int lrow = tid >> 2;           // 0..63
    int lk   = (tid & 3) * 4;      // 0,4,8,12
    const float* Ap = A + (size_t)(m0 + lrow) * K + lk;
    const float* Bp = B + (size_t)(n0 + lrow) * K + lk;

    for (int k0 = 0; k0 < K; k0 += BK) {
        float4 a = *(const float4*)(Ap + k0);
        float4 b = *(const float4*)(Bp + k0);
        As[lk+0][lrow] = a.x; As[lk+1][lrow] = a.y;
        As[lk+2][lrow] = a.z; As[lk+3][lrow] = a.w;
        Bs[lk+0][lrow] = b.x; Bs[lk+1][lrow] = b.y;
        Bs[lk+2][lrow] = b.z; Bs[lk+3][lrow] = b.w;
        __syncthreads();
        #pragma unroll
        for (int k = 0; k < BK; k++) {
            float4 av = *(const float4*)&As[k][ty*4];
            float4 bv = *(const float4*)&Bs[k][tx*4];
            float ar[4] = {av.x, av.y, av.z, av.w};
            float br[4] = {bv.x, bv.y, bv.z, bv.w};
            #pragma unroll
            for (int i = 0; i < 4; i++)
                #pragma unroll
                for (int j = 0; j < 4; j++)
                    acc[i][j] += ar[i] * br[j];
        }
        __syncthreads();
    }

    #pragma unroll
    for (int i = 0; i < 4; i++) {
        int m = m0 + ty*4 + i;
        #pragma unroll
        for (int j = 0; j < 4; j++) {
            int n = n0 + tx*4 + j;
            float v = acc[i][j] + (bias ? bias[n] : 0.0f);
            if (PERM == 0) {
                C[(size_t)m * N + n] = v;
            } else {
                int b = m / SEQ, s = m & (SEQ-1);
                int h = n / HD,  c = n & (HD-1);
                C[(((size_t)(b*HEADS + h))*SEQ + s)*HD + c] = v;
            }
        }
    }
}

// ---------------- Flash attention (causal), Br=Bc=64, fp32 ------------------
// Q,K,V in [BH, SEQ, HD]; output written to [B, S, D] for the final GEMM.
__global__ void __launch_bounds__(256) flash_attn_kernel(
    const float* __restrict__ Q, const float* __restrict__ K,
    const float* __restrict__ V, float* __restrict__ O)
{
    __shared__ float Qs [64][64];   // [kk][r]   (Q transposed)
    __shared__ float KPs[64][64];   // Ks[kk][j] during S; Ps[r][j] during PV
    __shared__ float Vs [64][64];   // [j][c]

    const float scale = 0.125f;     // 1/sqrt(64)
    int tid = threadIdx.x;
    int tx = tid & 15, ty = tid >> 4;
    int q0 = blockIdx.x * 64;
    int bh = blockIdx.y;

    const float* Qb = Q + (size_t)bh * SEQ * HD;
    const float* Kb = K + (size_t)bh * SEQ * HD;
    const float* Vb = V + (size_t)bh * SEQ * HD;

    // Load Q tile transposed: Qs[kk][r]
    {
        int r  = tid >> 2;
        int c0 = (tid & 3) * 16;
        const float* qrow = Qb + (size_t)(q0 + r) * HD + c0;
        #pragma unroll
        for (int u = 0; u < 4; u++) {
            float4 v = *(const float4*)(qrow + u*4);
            Qs[c0+u*4+0][r] = v.x; Qs[c0+u*4+1][r] = v.y;
            Qs[c0+u*4+2][r] = v.z; Qs[c0+u*4+3][r] = v.w;
        }
    }

    float o[4][4] = {};
    float mrow[4] = {-INFINITY, -INFINITY, -INFINITY, -INFINITY};
    float lrow[4] = {};

    int ktiles = blockIdx.x + 1;    // causal
    for (int t = 0; t < ktiles; t++) {
        int k0 = t * 64;
        __syncthreads();            // prior PV reads done before overwrite
        {
            int r  = tid >> 2;
            int c0 = (tid & 3) * 16;
            const float* krow = Kb + (size_t)(k0 + r) * HD + c0;
            const float* vrow = Vb + (size_t)(k0 + r) * HD + c0;
            #pragma unroll
            for (int u = 0; u < 4; u++) {
                float4 kv = *(const float4*)(krow + u*4);
                KPs[c0+u*4+0][r] = kv.x; KPs[c0+u*4+1][r] = kv.y;
                KPs[c0+u*4+2][r] = kv.z; KPs[c0+u*4+3][r] = kv.w;
                *(float4*)&Vs[r][c0+u*4] = *(const float4*)(vrow + u*4);
            }
        }
        __syncthreads();

        // S = Q K^T  (each thread: rows ty*4.., cols tx*4..)
        float s[4][4] = {};
        #pragma unroll
        for (int kk = 0; kk < 64; kk++) {
            float4 av = *(const float4*)&Qs[kk][ty*4];
            float4 bv = *(const float4*)&KPs[kk][tx*4];
            float ar[4] = {av.x, av.y, av.z, av.w};
            float br[4] = {bv.x, bv.y, bv.z, bv.w};
            #pragma unroll
            for (int i = 0; i < 4; i++)
                #pragma unroll
                for (int j = 0; j < 4; j++)
                    s[i][j] += ar[i] * br[j];
        }

        // scale + causal mask (only the diagonal tile needs masking)
        bool diag = (t == ktiles - 1);
        #pragma unroll
        for (int i = 0; i < 4; i++) {
            int qg = q0 + ty*4 + i;
            #pragma unroll
            for (int j = 0; j < 4; j++) {
                int kg = k0 + tx*4 + j;
                float v = s[i][j] * scale;
                if (diag && kg > qg) v = -1e30f;
                s[i][j] = v;
            }
        }

        // online softmax per row (reduce across the 16 lanes of a tx-group)
        #pragma unroll
        for (int i = 0; i < 4; i++) {
            float mx = fmaxf(fmaxf(s[i][0], s[i][1]), fmaxf(s[i][2], s[i][3]));
            #pragma unroll
            for (int off = 1; off < 16; off <<= 1)
                mx = fmaxf(mx, __shfl_xor_sync(0xffffffffu, mx, off));
            float mnew  = fmaxf(mrow[i], mx);
            float alpha = __expf(mrow[i] - mnew);
            mrow[i] = mnew;
            float ps = 0.0f;
            #pragma unroll
            for (int j = 0; j < 4; j++) {
                float p = __expf(s[i][j] - mnew);
                s[i][j] = p;
                ps += p;
            }
            #pragma unroll
            for (int off = 1; off < 16; off <<= 1)
                ps += __shfl_xor_sync(0xffffffffu, ps, off);
            lrow[i] = lrow[i] * alpha + ps;
            #pragma unroll
            for (int j = 0; j < 4; j++) o[i][j] *= alpha;
        }

        __syncthreads();            // all K reads done; reuse KPs for P
        #pragma unroll
        for (int i = 0; i < 4; i++)
            *(float4*)&KPs[ty*4 + i][tx*4] =
                make_float4(s[i][0], s[i][1], s[i][2], s[i][3]);
        __syncthreads();

        // O += P @ V
        #pragma unroll
        for (int j = 0; j < 64; j++) {
            float4 vv = *(const float4*)&Vs[j][tx*4];
            float vr[4] = {vv.x, vv.y, vv.z, vv.w};
            float p0 = KPs[ty*4+0][j];
            float p1 = KPs[ty*4+1][j];
            float p2 = KPs[ty*4+2][j];
            float p3 = KPs[ty*4+3][j];
            #pragma unroll
            for (int c = 0; c < 4; c++) {
                o[0][c] += p0 * vr[c];
                o[1][c] += p1 * vr[c];
                o[2][c] += p2 * vr[c];
                o[3][c] += p3 * vr[c];
            }
        }
    }

    // epilogue: normalize and write [B, S, D]
    int b = bh / HEADS, h = bh % HEADS;
    #pragma unroll
    for (int i = 0; i < 4; i++) {
        int r = q0 + ty*4 + i;
        float inv = 1.0f / lrow[i];
        #pragma unroll
        for (int j = 0; j < 4; j++) {
            O[((size_t)(b*SEQ + r)) * D_MODEL + h*HD + tx*4 + j] = o[i][j] * inv;
        }
    }
}

// ---------------- launch -----------------------------------------------------
extern "C" void kernel_launch(void* const* d_in, const int* in_sizes, int n_in,
                              void* d_out, int out_size) {
    const float* x   = (const float*)d_in[0];
    const float* Wq  = (const float*)d_in[1];
    const float* Wk  = (const float*)d_in[2];
    const float* Wv  = (const float*)d_in[3];
    const float* R   = (const float*)d_in[4];
    const float* ipw = (const float*)d_in[5];
    const float* ipb = (const float*)d_in[6];
    const float* ow  = (const float*)d_in[7];
    const float* ob  = (const float*)d_in[8];
    float* out = (float*)d_out;

    float *qkv, *heads, *attn, *tab;
    cudaGetSymbolAddress((void**)&qkv,   g_qkv);
    cudaGetSymbolAddress((void**)&heads, g_heads);
    cudaGetSymbolAddress((void**)&attn,  g_attn);
    cudaGetSymbolAddress((void**)&tab,   g_tab);

    const size_t MD = (size_t)MTOT * D_MODEL;   // per-matrix element count
    const size_t WW = (size_t)D_MODEL * D_MODEL;

    // 1) cos/sin table from R
    rope_table_kernel<<<SEQ, 256>>>(R, tab);

    // 2) q,k,v = x @ W{q,k,v}^T
    dim3 gg(D_MODEL/64, MTOT/64);
    sgemm_nt<0><<<gg, 256>>>(x, Wq, nullptr, qkv,          MTOT, D_MODEL, D_MODEL);
    sgemm_nt<0><<<gg, 256>>>(x, Wk, nullptr, qkv + MD,     MTOT, D_MODEL, D_MODEL);
    sgemm_nt<0><<<gg, 256>>>(x, Wv, nullptr, qkv + 2*MD,   MTOT, D_MODEL, D_MODEL);

    // 3) RoPE applied to q, k AND v (reference rotates all three)
    rope_apply_kernel<<<3*MTOT, 256>>>(qkv, tab);

    // 4) in_proj (with bias), fused permute to [B,H,S,HD]
    sgemm_nt<1><<<gg, 256>>>(qkv,        ipw,        ipb,             heads,        MTOT, D_MODEL, D_MODEL);
    sgemm_nt<1><<<gg, 256>>>(qkv + MD,   ipw + WW,   ipb + D_MODEL,   heads + MD,   MTOT, D_MODEL, D_MODEL);
    sgemm_nt<1><<<gg, 256>>>(qkv + 2*MD, ipw + 2*WW, ipb + 2*D_MODEL, heads + 2*MD, MTOT, D_MODEL, D_MODEL);

    // 5) causal flash attention -> [B, S, D]
    flash_attn_kernel<<<dim3(SEQ/64, BATCH*HEADS), 256>>>(
        heads, heads + MD, heads + 2*MD, attn);

    // 6) output projection
    sgemm_nt<0><<<gg, 256>>>(attn, ow, ob, out, MTOT, D_MODEL, D_MODEL);
}

// round 2
// speedup vs baseline: 1.1982x; 1.1982x over previous
#include <cuda_runtime.h>
#include <math.h>

#define D_MODEL 512
#define HEADS   8
#define HD      64
#define SEQ     2048
#define BATCH   4
#define MTOT    (BATCH*SEQ)   /* 8192 */
#define KDIM    512

// ---------------- scratch ----------------------------------------------------
__device__ float g_qkv[3][MTOT*D_MODEL];    // q,k,v after GEMM1 (RoPE fused)
__device__ float g_heads[3][MTOT*D_MODEL];  // qp,kp,vp in [B,H,S,HD]
__device__ float g_attn[MTOT*D_MODEL];      // attention output in [B,S,D]
__device__ float g_tab[SEQ*(D_MODEL/2)*2];  // (cos,sin) per (pos, pair)

// ---------------- RoPE table: gather cos/sin from dense R --------------------
__global__ void rope_table_kernel(const float* __restrict__ R, float* __restrict__ tab) {
    int i = threadIdx.x;              // pair 0..255
    int m = blockIdx.x;               // pos  0..2047
    const float* Rm = R + (size_t)m * D_MODEL * D_MODEL;
    float c = Rm[(size_t)(2*i)   * D_MODEL + 2*i];
    float s = Rm[(size_t)(2*i+1) * D_MODEL + 2*i];
    ((float2*)tab)[m*(D_MODEL/2) + i] = make_float2(c, s);
}

// ---------------- SGEMM 128x128, BK=16, 8x8 microtile, double-buffered -------
// C = A[M,K] @ B[N,K]^T (+bias)
// MODE 0: plain store (+bias)      MODE 1: head-permute store (+bias)
// MODE 2: RoPE epilogue, plain store (no bias)
// gridDim.z batches independent GEMMs (strides in elements).
template<int MODE>
__global__ void __launch_bounds__(256) sgemm128(
    const float* __restrict__ A, const float* __restrict__ Bm,
    const float* __restrict__ bias, float* __restrict__ C,
    const float* __restrict__ tab,
    long strideA, long strideB, long strideBias, long strideC)
{
    __shared__ float As[2][16][132];
    __shared__ float Bs[2][16][132];

    int z = blockIdx.z;
    A    += (size_t)z * strideA;
    Bm   += (size_t)z * strideB;
    C    += (size_t)z * strideC;
    if (bias) bias += (size_t)z * strideBias;

    int tid = threadIdx.x;
    int tx = tid & 15, ty = tid >> 4;
    int m0 = blockIdx.y * 128, n0 = blockIdx.x * 128;

    int lr = tid >> 2;            // 0..63
    int lk = (tid & 3) * 4;       // 0,4,8,12
    const float* Ap = A + (size_t)(m0 + lr) * KDIM + lk;
    const float* Bp = Bm + (size_t)(n0 + lr) * KDIM + lk;

    float acc[8][8] = {};

    // stage 0 direct to smem
    {
        float4 a0 = *(const float4*)(Ap);
        float4 a1 = *(const float4*)(Ap + 64*KDIM);
        float4 b0 = *(const float4*)(Bp);
        float4 b1 = *(const float4*)(Bp + 64*KDIM);
        #pragma unroll
        for (int w = 0; w < 4; w++) {
            As[0][lk+w][lr]    = ((const float*)&a0)[w];
            As[0][lk+w][lr+64] = ((const float*)&a1)[w];
            Bs[0][lk+w][lr]    = ((const float*)&b0)[w];
            Bs[0][lk+w][lr+64] = ((const float*)&b1)[w];
        }
    }
    __syncthreads();

    const int NS = KDIM / 16;     // 32
    float4 ra0, ra1, rb0, rb1;

    for (int s = 0; s < NS; s++) {
        int buf = s & 1;
        if (s + 1 < NS) {
            int ko = (s + 1) * 16;
            ra0 = *(const float4*)(Ap + ko);
            ra1 = *(const float4*)(Ap + 64*KDIM + ko);
            rb0 = *(const float4*)(Bp + ko);
            rb1 = *(const float4*)(Bp + 64*KDIM + ko);
        }
        #pragma unroll
        for (int k = 0; k < 16; k++) {
            float4 a0 = *(const float4*)&As[buf][k][ty*4];
            float4 a1 = *(const float4*)&As[buf][k][ty*4+64];
            float4 b0 = *(const float4*)&Bs[buf][k][tx*4];
            float4 b1 = *(const float4*)&Bs[buf][k][tx*4+64];
            float ar[8] = {a0.x,a0.y,a0.z,a0.w, a1.x,a1.y,a1.z,a1.w};
            float br[8] = {b0.x,b0.y,b0.z,b0.w, b1.x,b1.y,b1.z,b1.w};
            #pragma unroll
            for (int i = 0; i < 8; i++)
                #pragma unroll
                for (int j = 0; j < 8; j++)
                    acc[i][j] += ar[i] * br[j];
        }
        if (s + 1 < NS) {
            int nb = buf ^ 1;
            #pragma unroll
            for (int w = 0; w < 4; w++) {
                As[nb][lk+w][lr]    = ((const float*)&ra0)[w];
                As[nb][lk+w][lr+64] = ((const float*)&ra1)[w];
                Bs[nb][lk+w][lr]    = ((const float*)&rb0)[w];
                Bs[nb][lk+w][lr+64] = ((const float*)&rb1)[w];
            }
        }
        __syncthreads();
    }

    const float2* tab2 = (const float2*)tab;

    #pragma unroll
    for (int g = 0; g < 2; g++) {
        #pragma unroll
        for (int i = 0; i < 4; i++) {
            int m = m0 + ty*4 + g*64 + i;
            #pragma unroll
            for (int h = 0; h < 2; h++) {
                int n0g = n0 + tx*4 + h*64;
                float v0 = acc[g*4+i][h*4+0];
                float v1 = acc[g*4+i][h*4+1];
                float v2 = acc[g*4+i][h*4+2];
                float v3 = acc[g*4+i][h*4+3];
                if (MODE == 2) {
                    // RoPE on column pairs (n0g,n0g+1),(n0g+2,n0g+3); pos = m & 2047
                    int mm = m & (SEQ-1);
                    float2 cs0 = tab2[mm*(D_MODEL/2) + (n0g>>1)];
                    float2 cs1 = tab2[mm*(D_MODEL/2) + (n0g>>1) + 1];
                    float o0 =  v0*cs0.x + v1*cs0.y;
                    float o1 = -v0*cs0.y + v1*cs0.x;
                    float o2 =  v2*cs1.x + v3*cs1.y;
                    float o3 = -v2*cs1.y + v3*cs1.x;
                    v0=o0; v1=o1; v2=o2; v3=o3;
                } else if (bias) {
                    v0 += bias[n0g+0]; v1 += bias[n0g+1];
                    v2 += bias[n0g+2]; v3 += bias[n0g+3];
                }
                float4 outv = make_float4(v0,v1,v2,v3);
                if (MODE == 1) {
                    int b = m >> 11, s = m & (SEQ-1);
                    int hh = n0g >> 6, c = n0g & (HD-1);
                    *(float4*)&C[(((size_t)(b*HEADS + hh))*SEQ + s)*HD + c] = outv;
                } else {
                    *(float4*)&C[(size_t)m * D_MODEL + n0g] = outv;
                }
            }
        }
    }
}

// ---------------- Flash attention: Br=128, Bc=64, 8x4 microtile --------------
// Q,K,V in [BH, SEQ, HD]; output in [B, S, D].
#define QS_OFF   0
#define KT_OFF   (64*132)
#define VS_OFF   (KT_OFF + 64*68)
#define PS_OFF   (VS_OFF + 64*68)
#define ATT_SMEM ((PS_OFF + 128*68) * 4)

__global__ void __launch_bounds__(256) flash_attn2(
    const float* __restrict__ Q, const float* __restrict__ K,
    const float* __restrict__ V, float* __restrict__ O)
{
    extern __shared__ float sm[];
    float (*Qs)[132] = (float(*)[132])(sm + QS_OFF);  // Q^T  [64][128+pad]
    float (*Kt)[68]  = (float(*)[68]) (sm + KT_OFF);  // K^T  [64][64+pad]
    float (*Vs)[68]  = (float(*)[68]) (sm + VS_OFF);  // V    [64][64+pad]
    float (*Ps)[68]  = (float(*)[68]) (sm + PS_OFF);  // P    [128][64+pad]

    const float scale = 0.125f;
    int tid = threadIdx.x;
    int tx = tid & 15, ty = tid >> 4;
    int q0 = blockIdx.x * 128;
    int bh = blockIdx.y;

    const float* Qb = Q + (size_t)bh * SEQ * HD;
    const float* Kb = K + (size_t)bh * SEQ * HD;
    const float* Vb = V + (size_t)bh * SEQ * HD;

    // Load Q tile transposed: Qs[kk][r]
    {
        int r  = tid >> 1;            // 0..127
        int c0 = (tid & 1) * 32;
        const float* qrow = Qb + (size_t)(q0 + r) * HD + c0;
        #pragma unroll
        for (int u = 0; u < 8; u++) {
            float4 v = *(const float4*)(qrow + u*4);
            Qs[c0+u*4+0][r] = v.x; Qs[c0+u*4+1][r] = v.y;
            Qs[c0+u*4+2][r] = v.z; Qs[c0+u*4+3][r] = v.w;
        }
    }

    float o[8][4] = {};
    float mr[8], lr_[8];
    #pragma unroll
    for (int i = 0; i < 8; i++) { mr[i] = -INFINITY; lr_[i] = 0.0f; }

    int rows[8];
    #pragma unroll
    for (int i = 0; i < 8; i++) rows[i] = ty*4 + (i & 3) + (i >> 2)*64;

    int ktiles = 2*blockIdx.x + 2;
    for (int t = 0; t < ktiles; t++) {
        int k0 = t * 64;
        __syncthreads();              // prior PV reads done
        {
            int r  = tid >> 2;        // 0..63
            int c0 = (tid & 3) * 16;
            const float* krow = Kb + (size_t)(k0 + r) * HD + c0;
            const float* vrow = Vb + (size_t)(k0 + r) * HD + c0;
            #pragma unroll
            for (int u = 0; u < 4; u++) {
                float4 kv = *(const float4*)(krow + u*4);
                Kt[c0+u*4+0][r] = kv.x; Kt[c0+u*4+1][r] = kv.y;
                Kt[c0+u*4+2][r] = kv.z; Kt[c0+u*4+3][r] = kv.w;
                *(float4*)&Vs[r][c0+u*4] = *(const float4*)(vrow + u*4);
            }
        }
        __syncthreads();

        // S = Q K^T : rows[8] x cols tx*4..+3
        float s[8][4] = {};
        #pragma unroll
        for (int kk = 0; kk < 64; kk++) {
            float4 a0 = *(const float4*)&Qs[kk][ty*4];
            float4 a1 = *(const float4*)&Qs[kk][ty*4+64];
            float4 bv = *(const float4*)&Kt[kk][tx*4];
            float ar[8] = {a0.x,a0.y,a0.z,a0.w, a1.x,a1.y,a1.z,a1.w};
            float br[4] = {bv.x,bv.y,bv.z,bv.w};
            #pragma unroll
            for (int i = 0; i < 8; i++)
                #pragma unroll
                for (int j = 0; j < 4; j++)
                    s[i][j] += ar[i] * br[j];
        }

        bool need_mask = (t >= ktiles - 2);
        #pragma unroll
        for (int i = 0; i < 8; i++) {
            int qg = q0 + rows[i];
            #pragma unroll
            for (int j = 0; j < 4; j++) {
                float v = s[i][j] * scale;
                if (need_mask) {
                    int kg = k0 + tx*4 + j;
                    if (kg > qg) v = -1e30f;
                }
                s[i][j] = v;
            }
        }

        // online softmax per row (16-lane shfl groups)
        #pragma unroll
        for (int i = 0; i < 8; i++) {
            float mx = fmaxf(fmaxf(s[i][0], s[i][1]), fmaxf(s[i][2], s[i][3]));
            #pragma unroll
            for (int off = 1; off < 16; off <<= 1)
                mx = fmaxf(mx, __shfl_xor_sync(0xffffffffu, mx, off));
            float mnew  = fmaxf(mr[i], mx);
            float alpha = __expf(mr[i] - mnew);
            mr[i] = mnew;
            float ps = 0.0f;
            #pragma unroll
            for (int j = 0; j < 4; j++) {
                float p = __expf(s[i][j] - mnew);
                s[i][j] = p;
                ps += p;
            }
            #pragma unroll
            for (int off = 1; off < 16; off <<= 1)
                ps += __shfl_xor_sync(0xffffffffu, ps, off);
            lr_[i] = lr_[i] * alpha + ps;
            #pragma unroll
            for (int j = 0; j < 4; j++) o[i][j] *= alpha;
        }

        __syncthreads();              // all Kt reads done
        #pragma unroll
        for (int i = 0; i < 8; i++)
            *(float4*)&Ps[rows[i]][tx*4] = make_float4(s[i][0],s[i][1],s[i][2],s[i][3]);
        __syncthreads();

        // O += P @ V
        #pragma unroll
        for (int j0 = 0; j0 < 64; j0 += 4) {
            float4 vv[4];
            #pragma unroll
            for (int jj = 0; jj < 4; jj++)
                vv[jj] = *(const float4*)&Vs[j0+jj][tx*4];
            #pragma unroll
            for (int i = 0; i < 8; i++) {
                float4 p = *(const float4*)&Ps[rows[i]][j0];
                float pr[4] = {p.x, p.y, p.z, p.w};
                #pragma unroll
                for (int jj = 0; jj < 4; jj++) {
                    o[i][0] += pr[jj] * vv[jj].x;
                    o[i][1] += pr[jj] * vv[jj].y;
                    o[i][2] += pr[jj] * vv[jj].z;
                    o[i][3] += pr[jj] * vv[jj].w;
                }
            }
        }
    }

    // epilogue: normalize, write [B, S, D]
    int b = bh / HEADS, h = bh % HEADS;
    #pragma unroll
    for (int i = 0; i < 8; i++) {
        int r = q0 + rows[i];
        float inv = 1.0f / lr_[i];
        float4 outv = make_float4(o[i][0]*inv, o[i][1]*inv, o[i][2]*inv, o[i][3]*inv);
        *(float4*)&O[((size_t)(b*SEQ + r)) * D_MODEL + h*HD + tx*4] = outv;
    }
}

// ---------------- launch ------------------------------------------------------
extern "C" void kernel_launch(void* const* d_in, const int* in_sizes, int n_in,
                              void* d_out, int out_size) {
    const float* x   = (const float*)d_in[0];
    const float* Wq  = (const float*)d_in[1];
    const float* Wk  = (const float*)d_in[2];
    const float* Wv  = (const float*)d_in[3];
    const float* R   = (const float*)d_in[4];
    const float* ipw = (const float*)d_in[5];
    const float* ipb = (const float*)d_in[6];
    const float* ow  = (const float*)d_in[7];
    const float* ob  = (const float*)d_in[8];
    float* out = (float*)d_out;

    float *qkv, *heads, *attn, *tab;
    cudaGetSymbolAddress((void**)&qkv,   g_qkv);
    cudaGetSymbolAddress((void**)&heads, g_heads);
    cudaGetSymbolAddress((void**)&attn,  g_attn);
    cudaGetSymbolAddress((void**)&tab,   g_tab);

    cudaFuncSetAttribute(flash_attn2,
                         cudaFuncAttributeMaxDynamicSharedMemorySize, ATT_SMEM);

    const long MD = (long)MTOT * D_MODEL;
    const long WW = (long)D_MODEL * D_MODEL;

    // 1) cos/sin table
    rope_table_kernel<<<SEQ, 256>>>(R, tab);

    // 2) q,k,v = x @ W^T with fused RoPE
    dim3 gg(D_MODEL/128, MTOT/128);
    sgemm128<2><<<gg, 256>>>(x, Wq, nullptr, qkv,        tab, 0,0,0,0);
    sgemm128<2><<<gg, 256>>>(x, Wk, nullptr, qkv + MD,   tab, 0,0,0,0);
    sgemm128<2><<<gg, 256>>>(x, Wv, nullptr, qkv + 2*MD, tab, 0,0,0,0);

    // 3) in_proj (bias + head-permute), z-batched over q/k/v
    dim3 gi(D_MODEL/128, MTOT/128, 3);
    sgemm128<1><<<gi, 256>>>(qkv, ipw, ipb, heads, nullptr, MD, WW, D_MODEL, MD);

    // 4) causal flash attention
    flash_attn2<<<dim3(SEQ/128, BATCH*HEADS), 256, ATT_SMEM>>>(
        heads, heads + MD, heads + 2*MD, attn);

    // 5) output projection
    sgemm128<0><<<gg, 256>>>(attn, ow, ob, out, nullptr, 0,0,0,0);
}

// round 3
// speedup vs baseline: 1.2027x; 1.0038x over previous
#include <cuda_runtime.h>
#include <math.h>

#define D_MODEL 512
#define HEADS   8
#define HD      64
#define SEQ     2048
#define BATCH   4
#define MTOT    (BATCH*SEQ)   /* 8192 */
#define KDIM    512

// ---------------- scratch ----------------------------------------------------
__device__ float g_qkv[3][MTOT*D_MODEL];    // q,k,v after GEMM1 (RoPE fused)
__device__ float g_heads[3][MTOT*D_MODEL];  // qp,kp,vp in [B,H,S,HD]
__device__ float g_attn[MTOT*D_MODEL];      // attention output in [B,S,D]
__device__ float g_tab[SEQ*(D_MODEL/2)*2];  // (cos,sin) per (pos, pair)

// ---------------- RoPE table: gather cos/sin from dense R --------------------
__global__ void rope_table_kernel(const float* __restrict__ R, float* __restrict__ tab) {
    int i = threadIdx.x;              // pair 0..255
    int m = blockIdx.x;               // pos  0..2047
    const float* Rm = R + (size_t)m * D_MODEL * D_MODEL;
    float c = Rm[(size_t)(2*i)   * D_MODEL + 2*i];
    float s = Rm[(size_t)(2*i+1) * D_MODEL + 2*i];
    ((float2*)tab)[m*(D_MODEL/2) + i] = make_float2(c, s);
}

// ---------------- SGEMM 128x128, BK=16, 8x8 microtile, double-buffered -------
// C = A[M,K] @ B[N,K]^T (+bias)
// MODE 0: plain store (+bias)      MODE 1: head-permute store (+bias)
// MODE 2: RoPE epilogue, plain store (no bias)
// gridDim.z batches independent GEMMs (strides in elements).
template<int MODE>
__global__ void __launch_bounds__(256) sgemm128(
    const float* __restrict__ A, const float* __restrict__ Bm,
    const float* __restrict__ bias, float* __restrict__ C,
    const float* __restrict__ tab,
    long strideA, long strideB, long strideBias, long strideC)
{
    __shared__ float As[2][16][132];
    __shared__ float Bs[2][16][132];

    int z = blockIdx.z;
    A    += (size_t)z * strideA;
    Bm   += (size_t)z * strideB;
    C    += (size_t)z * strideC;
    if (bias) bias += (size_t)z * strideBias;

    int tid = threadIdx.x;
    int tx = tid & 15, ty = tid >> 4;
    int m0 = blockIdx.y * 128, n0 = blockIdx.x * 128;

    int lr = tid >> 2;            // 0..63
    int lk = (tid & 3) * 4;       // 0,4,8,12
    const float* Ap = A + (size_t)(m0 + lr) * KDIM + lk;
    const float* Bp = Bm + (size_t)(n0 + lr) * KDIM + lk;

    float acc[8][8] = {};

    // stage 0 direct to smem
    {
        float4 a0 = *(const float4*)(Ap);
        float4 a1 = *(const float4*)(Ap + 64*KDIM);
        float4 b0 = *(const float4*)(Bp);
        float4 b1 = *(const float4*)(Bp + 64*KDIM);
        #pragma unroll
        for (int w = 0; w < 4; w++) {
            As[0][lk+w][lr]    = ((const float*)&a0)[w];
            As[0][lk+w][lr+64] = ((const float*)&a1)[w];
            Bs[0][lk+w][lr]    = ((const float*)&b0)[w];
            Bs[0][lk+w][lr+64] = ((const float*)&b1)[w];
        }
    }
    __syncthreads();

    const int NS = KDIM / 16;     // 32
    float4 ra0, ra1, rb0, rb1;

    for (int s = 0; s < NS; s++) {
        int buf = s & 1;
        if (s + 1 < NS) {
            int ko = (s + 1) * 16;
            ra0 = *(const float4*)(Ap + ko);
            ra1 = *(const float4*)(Ap + 64*KDIM + ko);
            rb0 = *(const float4*)(Bp + ko);
            rb1 = *(const float4*)(Bp + 64*KDIM + ko);
        }
        #pragma unroll
        for (int k = 0; k < 16; k++) {
            float4 a0 = *(const float4*)&As[buf][k][ty*4];
            float4 a1 = *(const float4*)&As[buf][k][ty*4+64];
            float4 b0 = *(const float4*)&Bs[buf][k][tx*4];
            float4 b1 = *(const float4*)&Bs[buf][k][tx*4+64];
            float ar[8] = {a0.x,a0.y,a0.z,a0.w, a1.x,a1.y,a1.z,a1.w};
            float br[8] = {b0.x,b0.y,b0.z,b0.w, b1.x,b1.y,b1.z,b1.w};
            #pragma unroll
            for (int i = 0; i < 8; i++)
                #pragma unroll
                for (int j = 0; j < 8; j++)
                    acc[i][j] += ar[i] * br[j];
        }
        if (s + 1 < NS) {
            int nb = buf ^ 1;
            #pragma unroll
            for (int w = 0; w < 4; w++) {
                As[nb][lk+w][lr]    = ((const float*)&ra0)[w];
                As[nb][lk+w][lr+64] = ((const float*)&ra1)[w];
                Bs[nb][lk+w][lr]    = ((const float*)&rb0)[w];
                Bs[nb][lk+w][lr+64] = ((const float*)&rb1)[w];
            }
        }
        __syncthreads();
    }

    const float2* tab2 = (const float2*)tab;

    #pragma unroll
    for (int g = 0; g < 2; g++) {
        #pragma unroll
        for (int i = 0; i < 4; i++) {
            int m = m0 + ty*4 + g*64 + i;
            #pragma unroll
            for (int h = 0; h < 2; h++) {
                int n0g = n0 + tx*4 + h*64;
                float v0 = acc[g*4+i][h*4+0];
                float v1 = acc[g*4+i][h*4+1];
                float v2 = acc[g*4+i][h*4+2];
                float v3 = acc[g*4+i][h*4+3];
                if (MODE == 2) {
                    // RoPE on column pairs (n0g,n0g+1),(n0g+2,n0g+3); pos = m & 2047
                    int mm = m & (SEQ-1);
                    float2 cs0 = tab2[mm*(D_MODEL/2) + (n0g>>1)];
                    float2 cs1 = tab2[mm*(D_MODEL/2) + (n0g>>1) + 1];
                    float o0 =  v0*cs0.x + v1*cs0.y;
                    float o1 = -v0*cs0.y + v1*cs0.x;
                    float o2 =  v2*cs1.x + v3*cs1.y;
                    float o3 = -v2*cs1.y + v3*cs1.x;
                    v0=o0; v1=o1; v2=o2; v3=o3;
                } else if (bias) {
                    v0 += bias[n0g+0]; v1 += bias[n0g+1];
                    v2 += bias[n0g+2]; v3 += bias[n0g+3];
                }
                float4 outv = make_float4(v0,v1,v2,v3);
                if (MODE == 1) {
                    int b = m >> 11, s = m & (SEQ-1);
                    int hh = n0g >> 6, c = n0g & (HD-1);
                    *(float4*)&C[(((size_t)(b*HEADS + hh))*SEQ + s)*HD + c] = outv;
                } else {
                    *(float4*)&C[(size_t)m * D_MODEL + n0g] = outv;
                }
            }
        }
    }
}

// ---------------- Flash attention: Br=128, Bc=64, 8x4 microtile --------------
// Q,K,V in [BH, SEQ, HD]; output in [B, S, D].
#define QS_OFF   0
#define KT_OFF   (64*132)
#define VS_OFF   (KT_OFF + 64*68)
#define PS_OFF   (VS_OFF + 64*68)
#define ATT_SMEM ((PS_OFF + 128*68) * 4)

__global__ void __launch_bounds__(256) flash_attn2(
    const float* __restrict__ Q, const float* __restrict__ K,
    const float* __restrict__ V, float* __restrict__ O)
{
    extern __shared__ float sm[];
    float (*Qs)[132] = (float(*)[132])(sm + QS_OFF);  // Q^T  [64][128+pad]
    float (*Kt)[68]  = (float(*)[68]) (sm + KT_OFF);  // K^T  [64][64+pad]
    float (*Vs)[68]  = (float(*)[68]) (sm + VS_OFF);  // V    [64][64+pad]
    float (*Ps)[68]  = (float(*)[68]) (sm + PS_OFF);  // P    [128][64+pad]

    const float scale = 0.125f;
    int tid = threadIdx.x;
    int tx = tid & 15, ty = tid >> 4;
    int q0 = blockIdx.x * 128;
    int bh = blockIdx.y;

    const float* Qb = Q + (size_t)bh * SEQ * HD;
    const float* Kb = K + (size_t)bh * SEQ * HD;
    const float* Vb = V + (size_t)bh * SEQ * HD;

    // Load Q tile transposed: Qs[kk][r]
    {
        int r  = tid >> 1;            // 0..127
        int c0 = (tid & 1) * 32;
        const float* qrow = Qb + (size_t)(q0 + r) * HD + c0;
        #pragma unroll
        for (int u = 0; u < 8; u++) {
            float4 v = *(const float4*)(qrow + u*4);
            Qs[c0+u*4+0][r] = v.x; Qs[c0+u*4+1][r] = v.y;
            Qs[c0+u*4+2][r] = v.z; Qs[c0+u*4+3][r] = v.w;
        }
    }

    float o[8][4] = {};
    float mr[8], lr_[8];
    #pragma unroll
    for (int i = 0; i < 8; i++) { mr[i] = -INFINITY; lr_[i] = 0.0f; }

    int rows[8];
    #pragma unroll
    for (int i = 0; i < 8; i++) rows[i] = ty*4 + (i & 3) + (i >> 2)*64;

    int ktiles = 2*blockIdx.x + 2;
    for (int t = 0; t < ktiles; t++) {
        int k0 = t * 64;
        __syncthreads();              // prior PV reads done
        {
            int r  = tid >> 2;        // 0..63
            int c0 = (tid & 3) * 16;
            const float* krow = Kb + (size_t)(k0 + r) * HD + c0;
            const float* vrow = Vb + (size_t)(k0 + r) * HD + c0;
            #pragma unroll
            for (int u = 0; u < 4; u++) {
                float4 kv = *(const float4*)(krow + u*4);
                Kt[c0+u*4+0][r] = kv.x; Kt[c0+u*4+1][r] = kv.y;
                Kt[c0+u*4+2][r] = kv.z; Kt[c0+u*4+3][r] = kv.w;
                *(float4*)&Vs[r][c0+u*4] = *(const float4*)(vrow + u*4);
            }
        }
        __syncthreads();

        // S = Q K^T : rows[8] x cols tx*4..+3
        float s[8][4] = {};
        #pragma unroll
        for (int kk = 0; kk < 64; kk++) {
            float4 a0 = *(const float4*)&Qs[kk][ty*4];
            float4 a1 = *(const float4*)&Qs[kk][ty*4+64];
            float4 bv = *(const float4*)&Kt[kk][tx*4];
            float ar[8] = {a0.x,a0.y,a0.z,a0.w, a1.x,a1.y,a1.z,a1.w};
            float br[4] = {bv.x,bv.y,bv.z,bv.w};
            #pragma unroll
            for (int i = 0; i < 8; i++)
                #pragma unroll
                for (int j = 0; j < 4; j++)
                    s[i][j] += ar[i] * br[j];
        }

        bool need_mask = (t >= ktiles - 2);
        #pragma unroll
        for (int i = 0; i < 8; i++) {
            int qg = q0 + rows[i];
            #pragma unroll
            for (int j = 0; j < 4; j++) {
                float v = s[i][j] * scale;
                if (need_mask) {
                    int kg = k0 + tx*4 + j;
                    if (kg > qg) v = -1e30f;
                }
                s[i][j] = v;
            }
        }

        // online softmax per row (16-lane shfl groups)
        #pragma unroll
        for (int i = 0; i < 8; i++) {
            float mx = fmaxf(fmaxf(s[i][0], s[i][1]), fmaxf(s[i][2], s[i][3]));
            #pragma unroll
            for (int off = 1; off < 16; off <<= 1)
                mx = fmaxf(mx, __shfl_xor_sync(0xffffffffu, mx, off));
            float mnew  = fmaxf(mr[i], mx);
            float alpha = __expf(mr[i] - mnew);
            mr[i] = mnew;
            float ps = 0.0f;
            #pragma unroll
            for (int j = 0; j < 4; j++) {
                float p = __expf(s[i][j] - mnew);
                s[i][j] = p;
                ps += p;
            }
            #pragma unroll
            for (int off = 1; off < 16; off <<= 1)
                ps += __shfl_xor_sync(0xffffffffu, ps, off);
            lr_[i] = lr_[i] * alpha + ps;
            #pragma unroll
            for (int j = 0; j < 4; j++) o[i][j] *= alpha;
        }

        __syncthreads();              // all Kt reads done
        #pragma unroll
        for (int i = 0; i < 8; i++)
            *(float4*)&Ps[rows[i]][tx*4] = make_float4(s[i][0],s[i][1],s[i][2],s[i][3]);
        __syncthreads();

        // O += P @ V
        #pragma unroll
        for (int j0 = 0; j0 < 64; j0 += 4) {
            float4 vv[4];
            #pragma unroll
            for (int jj = 0; jj < 4; jj++)
                vv[jj] = *(const float4*)&Vs[j0+jj][tx*4];
            #pragma unroll
            for (int i = 0; i < 8; i++) {
                float4 p = *(const float4*)&Ps[rows[i]][j0];
                float pr[4] = {p.x, p.y, p.z, p.w};
                #pragma unroll
                for (int jj = 0; jj < 4; jj++) {
                    o[i][0] += pr[jj] * vv[jj].x;
                    o[i][1] += pr[jj] * vv[jj].y;
                    o[i][2] += pr[jj] * vv[jj].z;
                    o[i][3] += pr[jj] * vv[jj].w;
                }
            }
        }
    }

    // epilogue: normalize, write [B, S, D]
    int b = bh / HEADS, h = bh % HEADS;
    #pragma unroll
    for (int i = 0; i < 8; i++) {
        int r = q0 + rows[i];
        float inv = 1.0f / lr_[i];
        float4 outv = make_float4(o[i][0]*inv, o[i][1]*inv, o[i][2]*inv, o[i][3]*inv);
        *(float4*)&O[((size_t)(b*SEQ + r)) * D_MODEL + h*HD + tx*4] = outv;
    }
}

// ---------------- launch ------------------------------------------------------
extern "C" void kernel_launch(void* const* d_in, const int* in_sizes, int n_in,
                              void* d_out, int out_size) {
    const float* x   = (const float*)d_in[0];
    const float* Wq  = (const float*)d_in[1];
    const float* Wk  = (const float*)d_in[2];
    const float* Wv  = (const float*)d_in[3];
    const float* R   = (const float*)d_in[4];
    const float* ipw = (const float*)d_in[5];
    const float* ipb = (const float*)d_in[6];
    const float* ow  = (const float*)d_in[7];
    const float* ob  = (const float*)d_in[8];
    float* out = (float*)d_out;

    float *qkv, *heads, *attn, *tab;
    cudaGetSymbolAddress((void**)&qkv,   g_qkv);
    cudaGetSymbolAddress((void**)&heads, g_heads);
    cudaGetSymbolAddress((void**)&attn,  g_attn);
    cudaGetSymbolAddress((void**)&tab,   g_tab);

    cudaFuncSetAttribute(flash_attn2,
                         cudaFuncAttributeMaxDynamicSharedMemorySize, ATT_SMEM);

    const long MD = (long)MTOT * D_MODEL;
    const long WW = (long)D_MODEL * D_MODEL;

    // 1) cos/sin table
    rope_table_kernel<<<SEQ, 256>>>(R, tab);

    // 2) q,k,v = x @ W^T with fused RoPE
    dim3 gg(D_MODEL/128, MTOT/128);
    sgemm128<2><<<gg, 256>>>(x, Wq, nullptr, qkv,        tab, 0,0,0,0);
    sgemm128<2><<<gg, 256>>>(x, Wk, nullptr, qkv + MD,   tab, 0,0,0,0);
    sgemm128<2><<<gg, 256>>>(x, Wv, nullptr, qkv + 2*MD, tab, 0,0,0,0);

    // 3) in_proj (bias + head-permute), z-batched over q/k/v
    dim3 gi(D_MODEL/128, MTOT/128, 3);
    sgemm128<1><<<gi, 256>>>(qkv, ipw, ipb, heads, nullptr, MD, WW, D_MODEL, MD);

    // 4) causal flash attention
    flash_attn2<<<dim3(SEQ/128, BATCH*HEADS), 256, ATT_SMEM>>>(
        heads, heads + MD, heads + 2*MD, attn);

    // 5) output projection
    sgemm128<0><<<gg, 256>>>(attn, ow, ob, out, nullptr, 0,0,0,0);
}

// round 4
// speedup vs baseline: 1.5223x; 1.2657x over previous
#include <cuda_runtime.h>
#include <cuda_bf16.h>
#include <math.h>
#include <stdint.h>

#define D_MODEL 512
#define HEADS   8
#define HD      64
#define SEQ     2048
#define BATCH   4
#define MTOT    (BATCH*SEQ)   /* 8192 */
#define KDIM    512

// ---------------- scratch ----------------------------------------------------
__device__ float g_qkv[3][MTOT*D_MODEL];    // q,k,v after GEMM1 (RoPE fused)
__device__ float g_heads[3][MTOT*D_MODEL];  // qp,kp,vp in [B,H,S,HD]
__device__ float g_attn[MTOT*D_MODEL];      // attention output in [B,S,D]
__device__ float g_tab[SEQ*D_MODEL];        // (cos,sin) per (pos, pair)

// ---------------- helpers ------------------------------------------------------
__device__ __forceinline__ uint32_t packbf2(float lo, float hi){
    uint32_t r;
    asm("cvt.rn.bf16x2.f32 %0, %1, %2;" : "=r"(r) : "f"(hi), "f"(lo));
    return r;
}
// split fp32 pair (x low element, y high element) into bf16x2 hi + bf16x2 lo
__device__ __forceinline__ void split2(float x, float y, uint32_t& h, uint32_t& l){
    h = packbf2(x, y);
    float hx = __uint_as_float(h << 16);
    float hy = __uint_as_float(h & 0xffff0000u);
    l = packbf2(x - hx, y - hy);
}
__device__ __forceinline__ void ldsm_x4(uint32_t* r, uint32_t addr){
    asm volatile("ldmatrix.sync.aligned.m8n8.x4.shared.b16 {%0,%1,%2,%3}, [%4];"
        : "=r"(r[0]),"=r"(r[1]),"=r"(r[2]),"=r"(r[3]) : "r"(addr));
}
__device__ __forceinline__ void mma_bf16(float* c, const uint32_t* a, uint32_t b0, uint32_t b1){
    asm volatile("mma.sync.aligned.m16n8k16.row.col.f32.bf16.bf16.f32 "
        "{%0,%1,%2,%3},{%4,%5,%6,%7},{%8,%9},{%0,%1,%2,%3};"
        : "+f"(c[0]),"+f"(c[1]),"+f"(c[2]),"+f"(c[3])
        : "r"(a[0]),"r"(a[1]),"r"(a[2]),"r"(a[3]),"r"(b0),"r"(b1));
}

// ---------------- RoPE table: gather cos/sin from dense R --------------------
__global__ void rope_table_kernel(const float* __restrict__ R, float* __restrict__ tab){
    int i = threadIdx.x;              // pair 0..255
    int m = blockIdx.x;               // pos  0..2047
    const float* Rm = R + (size_t)m * D_MODEL * D_MODEL;
    float c = Rm[(size_t)(2*i)   * D_MODEL + 2*i];
    float s = Rm[(size_t)(2*i+1) * D_MODEL + 2*i];
    ((float2*)tab)[m*(D_MODEL/2) + i] = make_float2(c, s);
}

// ---------------- bf16x3 tensor-core GEMM: C = A @ B^T -----------------------
// A [M,512] fp32, B [512,512] fp32 (row = output col), split to bf16 hi/lo on load.
// Tile 128x128, BK=32, 8 warps (4x2), double buffered.
// MODE 0: +bias plain fp32   MODE 1: +bias head-permute fp32   MODE 2: RoPE fp32
// smem: 2 bufs x 4 regions x (128 rows x 20 uints) = 81920 B
#define REG_B   10240                      /* region stride bytes            */
#define BUF_B   40960                      /* buffer stride bytes            */
#define GEMM_SMEM 81920

template<int MODE>
__global__ void __launch_bounds__(256, 1) gemm_tc(
    const float* __restrict__ A, long sA,
    const float* __restrict__ B, long sB,
    const float* __restrict__ bias, long sBias,
    float* __restrict__ C, long sC,
    const float* __restrict__ tab)
{
    extern __shared__ uint32_t smu[];
    int z = blockIdx.z;
    A += (size_t)z * sA;  B += (size_t)z * sB;  C += (size_t)z * sC;
    if (bias) bias += (size_t)z * sBias;

    int tid  = threadIdx.x;
    int lane = tid & 31, wid = tid >> 5;
    int warp_m = wid >> 1, warp_n = wid & 1;      // 4 x 2 warps
    int m0 = blockIdx.y * 128, n0 = blockIdx.x * 128;

    int lrow = tid >> 1;          // 0..127
    int half = tid & 1;           // 16-float half of the 32-float stage chunk
    const float* Ag = A + (size_t)(m0 + lrow) * KDIM + half * 16;
    const float* Bg = B + (size_t)(n0 + lrow) * KDIM + half * 16;

    uint32_t smb = (uint32_t)__cvta_generic_to_shared(smu);
    // store offsets (uint indices)
    uint32_t soff = lrow * 20 + half * 8;

    float4 rA[4], rB[4];

    auto stage_store = [&](int buf){
        uint32_t* base = smu + buf * (BUF_B/4);
        uint32_t ah[8], al[8], bh[8], bl[8];
        #pragma unroll
        for (int u = 0; u < 4; u++){
            split2(rA[u].x, rA[u].y, ah[u*2],   al[u*2]);
            split2(rA[u].z, rA[u].w, ah[u*2+1], al[u*2+1]);
            split2(rB[u].x, rB[u].y, bh[u*2],   bl[u*2]);
            split2(rB[u].z, rB[u].w, bh[u*2+1], bl[u*2+1]);
        }
        *(uint4*)(base + soff)                = make_uint4(ah[0],ah[1],ah[2],ah[3]);
        *(uint4*)(base + soff + 4)            = make_uint4(ah[4],ah[5],ah[6],ah[7]);
        *(uint4*)(base + REG_B/4 + soff)      = make_uint4(al[0],al[1],al[2],al[3]);
        *(uint4*)(base + REG_B/4 + soff + 4)  = make_uint4(al[4],al[5],al[6],al[7]);
        *(uint4*)(base + 2*REG_B/4 + soff)    = make_uint4(bh[0],bh[1],bh[2],bh[3]);
        *(uint4*)(base + 2*REG_B/4 + soff + 4)= make_uint4(bh[4],bh[5],bh[6],bh[7]);
        *(uint4*)(base + 3*REG_B/4 + soff)    = make_uint4(bl[0],bl[1],bl[2],bl[3]);
        *(uint4*)(base + 3*REG_B/4 + soff + 4)= make_uint4(bl[4],bl[5],bl[6],bl[7]);
    };
    auto stage_load = [&](int s){
        #pragma unroll
        for (int u = 0; u < 4; u++){
            rA[u] = *(const float4*)(Ag + s*32 + u*4);
            rB[u] = *(const float4*)(Bg + s*32 + u*4);
        }
    };

    stage_load(0);
    stage_store(0);
    __syncthreads();

    float acc[2][8][4] = {};
    // ldmatrix lane address bases (byte offsets into a buffer)
    uint32_t a_base = (uint32_t)((warp_m*32 + (lane & 15)) * 80 + (lane >> 4) * 16);
    uint32_t b_base = (uint32_t)((warp_n*64 + (lane & 15)) * 80 + (lane >> 4) * 16);

    const int NS = KDIM / 32;     // 16 stages
    for (int s = 0; s < NS; s++){
        int buf = s & 1;
        if (s + 1 < NS) stage_load(s + 1);
        uint32_t bb = smb + buf * BUF_B;
        #pragma unroll
        for (int kk = 0; kk < 2; kk++){
            uint32_t ko = kk * 32;
            uint32_t AH[2][4], AL[2][4], BH[4][4], BL[4][4];
            #pragma unroll
            for (int mi = 0; mi < 2; mi++){
                uint32_t aa = bb + a_base + mi*16*80 + ko;
                ldsm_x4(AH[mi], aa);
                ldsm_x4(AL[mi], aa + REG_B);
            }
            #pragma unroll
            for (int nb = 0; nb < 4; nb++){
                uint32_t ba = bb + 2*REG_B + b_base + nb*16*80 + ko;
                ldsm_x4(BH[nb], ba);
                ldsm_x4(BL[nb], ba + REG_B);
            }
            #pragma unroll
            for (int mi = 0; mi < 2; mi++)
                #pragma unroll
                for (int nb = 0; nb < 4; nb++){
                    // n-frag 2nb   : B regs {r0, r2};  n-frag 2nb+1 : {r1, r3}
                    mma_bf16(acc[mi][2*nb],   AH[mi], BH[nb][0], BH[nb][2]);
                    mma_bf16(acc[mi][2*nb],   AH[mi], BL[nb][0], BL[nb][2]);
                    mma_bf16(acc[mi][2*nb],   AL[mi], BH[nb][0], BH[nb][2]);
                    mma_bf16(acc[mi][2*nb+1], AH[mi], BH[nb][1], BH[nb][3]);
                    mma_bf16(acc[mi][2*nb+1], AH[mi], BL[nb][1], BL[nb][3]);
                    mma_bf16(acc[mi][2*nb+1], AL[mi], BH[nb][1], BH[nb][3]);
                }
        }
        if (s + 1 < NS) stage_store(buf ^ 1);
        __syncthreads();
    }

    // ---------------- epilogue ----------------
    const float2* tab2 = (const float2*)tab;
    #pragma unroll
    for (int mi = 0; mi < 2; mi++){
        #pragma unroll
        for (int ni = 0; ni < 8; ni++){
            int m = m0 + warp_m*32 + mi*16 + (lane >> 2);
            int n = n0 + warp_n*64 + ni*8 + (lane & 3)*2;
            float v0 = acc[mi][ni][0], v1 = acc[mi][ni][1];   // row m
            float v2 = acc[mi][ni][2], v3 = acc[mi][ni][3];   // row m+8
            if (MODE == 2){
                float2 cs0 = tab2[(m     & (SEQ-1)) * (D_MODEL/2) + (n >> 1)];
                float2 cs1 = tab2[((m+8) & (SEQ-1)) * (D_MODEL/2) + (n >> 1)];
                float o0 =  v0*cs0.x + v1*cs0.y;
                float o1 = -v0*cs0.y + v1*cs0.x;
                float o2 =  v2*cs1.x + v3*cs1.y;
                float o3 = -v2*cs1.y + v3*cs1.x;
                v0=o0; v1=o1; v2=o2; v3=o3;
            } else {
                float b0 = bias[n], b1 = bias[n+1];
                v0 += b0; v1 += b1; v2 += b0; v3 += b1;
            }
            if (MODE == 1){
                int b = m >> 11, sq = m & (SEQ-1);
                int hh = n >> 6,  c = n & (HD-1);
                size_t r0i = (((size_t)(b*HEADS + hh))*SEQ + sq)*HD + c;
                *(float2*)&C[r0i]          = make_float2(v0, v1);
                *(float2*)&C[r0i + 8*HD]   = make_float2(v2, v3);
            } else {
                *(float2*)&C[(size_t)m*D_MODEL + n]       = make_float2(v0, v1);
                *(float2*)&C[(size_t)(m+8)*D_MODEL + n]   = make_float2(v2, v3);
            }
        }
    }
}

// ---------------- Flash attention (unchanged, fp32, round-2 proven) ----------
#define QS_OFF   0
#define KT_OFF   (64*132)
#define VS_OFF   (KT_OFF + 64*68)
#define PS_OFF   (VS_OFF + 64*68)
#define ATT_SMEM ((PS_OFF + 128*68) * 4)

__global__ void __launch_bounds__(256) flash_attn2(
    const float* __restrict__ Q, const float* __restrict__ K,
    const float* __restrict__ V, float* __restrict__ O)
{
    extern __shared__ float sm[];
    float (*Qs)[132] = (float(*)[132])(sm + QS_OFF);
    float (*Kt)[68]  = (float(*)[68]) (sm + KT_OFF);
    float (*Vs)[68]  = (float(*)[68]) (sm + VS_OFF);
    float (*Ps)[68]  = (float(*)[68]) (sm + PS_OFF);

    const float scale = 0.125f;
    int tid = threadIdx.x;
    int tx = tid & 15, ty = tid >> 4;
    int q0 = blockIdx.x * 128;
    int bh = blockIdx.y;

    const float* Qb = Q + (size_t)bh * SEQ * HD;
    const float* Kb = K + (size_t)bh * SEQ * HD;
    const float* Vb = V + (size_t)bh * SEQ * HD;

    {
        int r  = tid >> 1;
        int c0 = (tid & 1) * 32;
        const float* qrow = Qb + (size_t)(q0 + r) * HD + c0;
        #pragma unroll
        for (int u = 0; u < 8; u++) {
            float4 v = *(const float4*)(qrow + u*4);
            Qs[c0+u*4+0][r] = v.x; Qs[c0+u*4+1][r] = v.y;
            Qs[c0+u*4+2][r] = v.z; Qs[c0+u*4+3][r] = v.w;
        }
    }

    float o[8][4] = {};
    float mr[8], lr_[8];
    #pragma unroll
    for (int i = 0; i < 8; i++) { mr[i] = -INFINITY; lr_[i] = 0.0f; }

    int rows[8];
    #pragma unroll
    for (int i = 0; i < 8; i++) rows[i] = ty*4 + (i & 3) + (i >> 2)*64;

    int ktiles = 2*blockIdx.x + 2;
    for (int t = 0; t < ktiles; t++) {
        int k0 = t * 64;
        __syncthreads();
        {
            int r  = tid >> 2;
            int c0 = (tid & 3) * 16;
            const float* krow = Kb + (size_t)(k0 + r) * HD + c0;
            const float* vrow = Vb + (size_t)(k0 + r) * HD + c0;
            #pragma unroll
            for (int u = 0; u < 4; u++) {
                float4 kv = *(const float4*)(krow + u*4);
                Kt[c0+u*4+0][r] = kv.x; Kt[c0+u*4+1][r] = kv.y;
                Kt[c0+u*4+2][r] = kv.z; Kt[c0+u*4+3][r] = kv.w;
                *(float4*)&Vs[r][c0+u*4] = *(const float4*)(vrow + u*4);
            }
        }
        __syncthreads();

        float s[8][4] = {};
        #pragma unroll
        for (int kk = 0; kk < 64; kk++) {
            float4 a0 = *(const float4*)&Qs[kk][ty*4];
            float4 a1 = *(const float4*)&Qs[kk][ty*4+64];
            float4 bv = *(const float4*)&Kt[kk][tx*4];
            float ar[8] = {a0.x,a0.y,a0.z,a0.w, a1.x,a1.y,a1.z,a1.w};
            float br[4] = {bv.x,bv.y,bv.z,bv.w};
            #pragma unroll
            for (int i = 0; i < 8; i++)
                #pragma unroll
                for (int j = 0; j < 4; j++)
                    s[i][j] += ar[i] * br[j];
        }

        bool need_mask = (t >= ktiles - 2);
        #pragma unroll
        for (int i = 0; i < 8; i++) {
            int qg = q0 + rows[i];
            #pragma unroll
            for (int j = 0; j < 4; j++) {
                float v = s[i][j] * scale;
                if (need_mask) {
                    int kg = k0 + tx*4 + j;
                    if (kg > qg) v = -1e30f;
                }
                s[i][j] = v;
            }
        }

        #pragma unroll
        for (int i = 0; i < 8; i++) {
            float mx = fmaxf(fmaxf(s[i][0], s[i][1]), fmaxf(s[i][2], s[i][3]));
            #pragma unroll
            for (int off = 1; off < 16; off <<= 1)
                mx = fmaxf(mx, __shfl_xor_sync(0xffffffffu, mx, off));
            float mnew  = fmaxf(mr[i], mx);
            float alpha = __expf(mr[i] - mnew);
            mr[i] = mnew;
            float ps = 0.0f;
            #pragma unroll
            for (int j = 0; j < 4; j++) {
                float p = __expf(s[i][j] - mnew);
                s[i][j] = p;
                ps += p;
            }
            #pragma unroll
            for (int off = 1; off < 16; off <<= 1)
                ps += __shfl_xor_sync(0xffffffffu, ps, off);
            lr_[i] = lr_[i] * alpha + ps;
            #pragma unroll
            for (int j = 0; j < 4; j++) o[i][j] *= alpha;
        }

        __syncthreads();
        #pragma unroll
        for (int i = 0; i < 8; i++)
            *(float4*)&Ps[rows[i]][tx*4] = make_float4(s[i][0],s[i][1],s[i][2],s[i][3]);
        __syncthreads();

        #pragma unroll
        for (int j0 = 0; j0 < 64; j0 += 4) {
            float4 vv[4];
            #pragma unroll
            for (int jj = 0; jj < 4; jj++)
                vv[jj] = *(const float4*)&Vs[j0+jj][tx*4];
            #pragma unroll
            for (int i = 0; i < 8; i++) {
                float4 p = *(const float4*)&Ps[rows[i]][j0];
                float pr[4] = {p.x, p.y, p.z, p.w};
                #pragma unroll
                for (int jj = 0; jj < 4; jj++) {
                    o[i][0] += pr[jj] * vv[jj].x;
                    o[i][1] += pr[jj] * vv[jj].y;
                    o[i][2] += pr[jj] * vv[jj].z;
                    o[i][3] += pr[jj] * vv[jj].w;
                }
            }
        }
    }

    int b = bh / HEADS, h = bh % HEADS;
    #pragma unroll
    for (int i = 0; i < 8; i++) {
        int r = q0 + rows[i];
        float inv = 1.0f / lr_[i];
        float4 outv = make_float4(o[i][0]*inv, o[i][1]*inv, o[i][2]*inv, o[i][3]*inv);
        *(float4*)&O[((size_t)(b*SEQ + r)) * D_MODEL + h*HD + tx*4] = outv;
    }
}

// ---------------- launch ------------------------------------------------------
extern "C" void kernel_launch(void* const* d_in, const int* in_sizes, int n_in,
                              void* d_out, int out_size) {
    const float* x   = (const float*)d_in[0];
    const float* Wq  = (const float*)d_in[1];
    const float* Wk  = (const float*)d_in[2];
    const float* Wv  = (const float*)d_in[3];
    const float* R   = (const float*)d_in[4];
    const float* ipw = (const float*)d_in[5];
    const float* ipb = (const float*)d_in[6];
    const float* ow  = (const float*)d_in[7];
    const float* ob  = (const float*)d_in[8];
    float* out = (float*)d_out;

    float *qkv, *heads, *attn, *tab;
    cudaGetSymbolAddress((void**)&qkv,   g_qkv);
    cudaGetSymbolAddress((void**)&heads, g_heads);
    cudaGetSymbolAddress((void**)&attn,  g_attn);
    cudaGetSymbolAddress((void**)&tab,   g_tab);

    static int inited = 0;
    if (!inited) {
        cudaFuncSetAttribute(gemm_tc<0>, cudaFuncAttributeMaxDynamicSharedMemorySize, GEMM_SMEM);
        cudaFuncSetAttribute(gemm_tc<1>, cudaFuncAttributeMaxDynamicSharedMemorySize, GEMM_SMEM);
        cudaFuncSetAttribute(gemm_tc<2>, cudaFuncAttributeMaxDynamicSharedMemorySize, GEMM_SMEM);
        cudaFuncSetAttribute(flash_attn2, cudaFuncAttributeMaxDynamicSharedMemorySize, ATT_SMEM);
        inited = 1;
    }

    const long MD = (long)MTOT * D_MODEL;
    const long WW = (long)D_MODEL * D_MODEL;

    // 1) cos/sin table
    rope_table_kernel<<<SEQ, 256>>>(R, tab);

    // 2) q,k,v = x @ W^T with fused RoPE  (z picks weight; A shared)
    dim3 gq(D_MODEL/128, MTOT/128, 1);
    gemm_tc<2><<<gq, 256, GEMM_SMEM>>>(x, 0, Wq, 0, nullptr, 0, qkv,        0, tab);
    gemm_tc<2><<<gq, 256, GEMM_SMEM>>>(x, 0, Wk, 0, nullptr, 0, qkv + MD,   0, tab);
    gemm_tc<2><<<gq, 256, GEMM_SMEM>>>(x, 0, Wv, 0, nullptr, 0, qkv + 2*MD, 0, tab);

    // 3) in_proj (bias + head-permute), z-batched over q/k/v
    dim3 gi(D_MODEL/128, MTOT/128, 3);
    gemm_tc<1><<<gi, 256, GEMM_SMEM>>>(qkv, MD, ipw, WW, ipb, D_MODEL, heads, MD, nullptr);

    // 4) causal flash attention (fp32)
    flash_attn2<<<dim3(SEQ/128, BATCH*HEADS), 256, ATT_SMEM>>>(
        heads, heads + MD, heads + 2*MD, attn);

    // 5) output projection
    dim3 go(D_MODEL/128, MTOT/128, 1);
    gemm_tc<0><<<go, 256, GEMM_SMEM>>>(attn, 0, ow, 0, ob, 0, out, 0, nullptr);
}

// round 5
// speedup vs baseline: 2.4565x; 1.6137x over previous
#include <cuda_runtime.h>
#include <cuda_bf16.h>
#include <math.h>
#include <stdint.h>

#define D_MODEL 512
#define HEADS   8
#define HD      64
#define SEQ     2048
#define BATCH   4
#define MTOT    (BATCH*SEQ)   /* 8192 */
#define KDIM    512
#define BH      (BATCH*HEADS) /* 32 */

// ---------------- scratch ----------------------------------------------------
__device__ float g_qkv[3][MTOT*D_MODEL];      // q,k,v after GEMM1 (RoPE fused)
__device__ uint32_t g_hh[3][MTOT*(D_MODEL/2)];// heads bf16-hi packed [BH][S][HD/2]
__device__ uint32_t g_hl[3][MTOT*(D_MODEL/2)];// heads bf16-lo
__device__ float g_attn[MTOT*D_MODEL];        // attention output [B,S,D]
__device__ float g_tab[SEQ*D_MODEL];          // (cos,sin) per (pos,pair)

// ---------------- helpers ------------------------------------------------------
__device__ __forceinline__ uint32_t packbf2(float lo, float hi){
    uint32_t r;
    asm("cvt.rn.bf16x2.f32 %0, %1, %2;" : "=r"(r) : "f"(hi), "f"(lo));
    return r;
}
__device__ __forceinline__ void split2(float x, float y, uint32_t& h, uint32_t& l){
    h = packbf2(x, y);
    float hx = __uint_as_float(h << 16);
    float hy = __uint_as_float(h & 0xffff0000u);
    l = packbf2(x - hx, y - hy);
}
__device__ __forceinline__ void ldsm_x4(uint32_t* r, uint32_t addr){
    asm volatile("ldmatrix.sync.aligned.m8n8.x4.shared.b16 {%0,%1,%2,%3}, [%4];"
        : "=r"(r[0]),"=r"(r[1]),"=r"(r[2]),"=r"(r[3]) : "r"(addr));
}
__device__ __forceinline__ void ldsm_x4t(uint32_t* r, uint32_t addr){
    asm volatile("ldmatrix.sync.aligned.m8n8.x4.trans.shared.b16 {%0,%1,%2,%3}, [%4];"
        : "=r"(r[0]),"=r"(r[1]),"=r"(r[2]),"=r"(r[3]) : "r"(addr));
}
__device__ __forceinline__ void mma_bf16(float* c, const uint32_t* a, uint32_t b0, uint32_t b1){
    asm volatile("mma.sync.aligned.m16n8k16.row.col.f32.bf16.bf16.f32 "
        "{%0,%1,%2,%3},{%4,%5,%6,%7},{%8,%9},{%0,%1,%2,%3};"
        : "+f"(c[0]),"+f"(c[1]),"+f"(c[2]),"+f"(c[3])
        : "r"(a[0]),"r"(a[1]),"r"(a[2]),"r"(a[3]),"r"(b0),"r"(b1));
}

// ---------------- RoPE table ---------------------------------------------------
__global__ void rope_table_kernel(const float* __restrict__ R, float* __restrict__ tab){
    int i = threadIdx.x;
    int m = blockIdx.x;
    const float* Rm = R + (size_t)m * D_MODEL * D_MODEL;
    float c = Rm[(size_t)(2*i)   * D_MODEL + 2*i];
    float s = Rm[(size_t)(2*i+1) * D_MODEL + 2*i];
    ((float2*)tab)[m*(D_MODEL/2) + i] = make_float2(c, s);
}

// ---------------- bf16x3 tensor-core GEMM: C = A @ B^T -----------------------
// MODE 0: +bias plain fp32  MODE 1: +bias, head-permute, packed bf16 hi/lo out
// MODE 2: RoPE epilogue, plain fp32
#define REG_B   10240
#define BUF_B   40960
#define GEMM_SMEM 81920

template<int MODE>
__global__ void __launch_bounds__(256, 1) gemm_tc(
    const float* __restrict__ A, long sA,
    const float* __restrict__ B, long sB,
    const float* __restrict__ bias, long sBias,
    float* __restrict__ Cf, uint32_t* __restrict__ Ch, uint32_t* __restrict__ Cl,
    long sC, const float* __restrict__ tab)
{
    extern __shared__ uint32_t smu[];
    int z = blockIdx.z;
    A += (size_t)z * sA;  B += (size_t)z * sB;
    if (bias) bias += (size_t)z * sBias;

    int tid  = threadIdx.x;
    int lane = tid & 31, wid = tid >> 5;
    int warp_m = wid >> 1, warp_n = wid & 1;
    int m0 = blockIdx.y * 128, n0 = blockIdx.x * 128;

    int lrow = tid >> 1;
    int half = tid & 1;
    const float* Ag = A + (size_t)(m0 + lrow) * KDIM + half * 16;
    const float* Bg = B + (size_t)(n0 + lrow) * KDIM + half * 16;

    uint32_t smb = (uint32_t)__cvta_generic_to_shared(smu);
    uint32_t soff = lrow * 20 + half * 8;

    float4 rA[4], rB[4];

    auto stage_store = [&](int buf){
        uint32_t* base = smu + buf * (BUF_B/4);
        uint32_t ah[8], al[8], bh[8], bl[8];
        #pragma unroll
        for (int u = 0; u < 4; u++){
            split2(rA[u].x, rA[u].y, ah[u*2],   al[u*2]);
            split2(rA[u].z, rA[u].w, ah[u*2+1], al[u*2+1]);
            split2(rB[u].x, rB[u].y, bh[u*2],   bl[u*2]);
            split2(rB[u].z, rB[u].w, bh[u*2+1], bl[u*2+1]);
        }
        *(uint4*)(base + soff)                = make_uint4(ah[0],ah[1],ah[2],ah[3]);
        *(uint4*)(base + soff + 4)            = make_uint4(ah[4],ah[5],ah[6],ah[7]);
        *(uint4*)(base + REG_B/4 + soff)      = make_uint4(al[0],al[1],al[2],al[3]);
        *(uint4*)(base + REG_B/4 + soff + 4)  = make_uint4(al[4],al[5],al[6],al[7]);
        *(uint4*)(base + 2*REG_B/4 + soff)    = make_uint4(bh[0],bh[1],bh[2],bh[3]);
        *(uint4*)(base + 2*REG_B/4 + soff + 4)= make_uint4(bh[4],bh[5],bh[6],bh[7]);
        *(uint4*)(base + 3*REG_B/4 + soff)    = make_uint4(bl[0],bl[1],bl[2],bl[3]);
        *(uint4*)(base + 3*REG_B/4 + soff + 4)= make_uint4(bl[4],bl[5],bl[6],bl[7]);
    };
    auto stage_load = [&](int s){
        #pragma unroll
        for (int u = 0; u < 4; u++){
            rA[u] = *(const float4*)(Ag + s*32 + u*4);
            rB[u] = *(const float4*)(Bg + s*32 + u*4);
        }
    };

    stage_load(0);
    stage_store(0);
    __syncthreads();

    float acc[2][8][4] = {};
    uint32_t a_base = (uint32_t)((warp_m*32 + (lane & 15)) * 80 + (lane >> 4) * 16);
    uint32_t b_base = (uint32_t)((warp_n*64 + (lane & 15)) * 80 + (lane >> 4) * 16);

    const int NS = KDIM / 32;
    for (int s = 0; s < NS; s++){
        int buf = s & 1;
        if (s + 1 < NS) stage_load(s + 1);
        uint32_t bb = smb + buf * BUF_B;
        #pragma unroll
        for (int kk = 0; kk < 2; kk++){
            uint32_t ko = kk * 32;
            uint32_t AH[2][4], AL[2][4], BHH[4][4], BLL[4][4];
            #pragma unroll
            for (int mi = 0; mi < 2; mi++){
                uint32_t aa = bb + a_base + mi*16*80 + ko;
                ldsm_x4(AH[mi], aa);
                ldsm_x4(AL[mi], aa + REG_B);
            }
            #pragma unroll
            for (int nb = 0; nb < 4; nb++){
                uint32_t ba = bb + 2*REG_B + b_base + nb*16*80 + ko;
                ldsm_x4(BHH[nb], ba);
                ldsm_x4(BLL[nb], ba + REG_B);
            }
            #pragma unroll
            for (int mi = 0; mi < 2; mi++)
                #pragma unroll
                for (int nb = 0; nb < 4; nb++){
                    mma_bf16(acc[mi][2*nb],   AH[mi], BHH[nb][0], BHH[nb][2]);
                    mma_bf16(acc[mi][2*nb],   AH[mi], BLL[nb][0], BLL[nb][2]);
                    mma_bf16(acc[mi][2*nb],   AL[mi], BHH[nb][0], BHH[nb][2]);
                    mma_bf16(acc[mi][2*nb+1], AH[mi], BHH[nb][1], BHH[nb][3]);
                    mma_bf16(acc[mi][2*nb+1], AH[mi], BLL[nb][1], BLL[nb][3]);
                    mma_bf16(acc[mi][2*nb+1], AL[mi], BHH[nb][1], BHH[nb][3]);
                }
        }
        if (s + 1 < NS) stage_store(buf ^ 1);
        __syncthreads();
    }

    const float2* tab2 = (const float2*)tab;
    #pragma unroll
    for (int mi = 0; mi < 2; mi++){
        #pragma unroll
        for (int ni = 0; ni < 8; ni++){
            int m = m0 + warp_m*32 + mi*16 + (lane >> 2);
            int n = n0 + warp_n*64 + ni*8 + (lane & 3)*2;
            float v0 = acc[mi][ni][0], v1 = acc[mi][ni][1];   // row m
            float v2 = acc[mi][ni][2], v3 = acc[mi][ni][3];   // row m+8
            if (MODE == 2){
                float2 cs0 = tab2[(m     & (SEQ-1)) * (D_MODEL/2) + (n >> 1)];
                float2 cs1 = tab2[((m+8) & (SEQ-1)) * (D_MODEL/2) + (n >> 1)];
                float o0 =  v0*cs0.x + v1*cs0.y;
                float o1 = -v0*cs0.y + v1*cs0.x;
                float o2 =  v2*cs1.x + v3*cs1.y;
                float o3 = -v2*cs1.y + v3*cs1.x;
                v0=o0; v1=o1; v2=o2; v3=o3;
            } else {
                float b0 = bias[n], b1 = bias[n+1];
                v0 += b0; v1 += b1; v2 += b0; v3 += b1;
            }
            if (MODE == 1){
                // head-permute + packed bf16 hi/lo out: [BH][S][HD/2]
                int b = m >> 11, sq = m & (SEQ-1);
                int hh = n >> 6,  c = n & (HD-1);
                size_t i0 = (((size_t)(b*HEADS + hh))*SEQ + sq)*(HD/2) + (c>>1);
                uint32_t h0,l0,h1,l1;
                split2(v0, v1, h0, l0);
                split2(v2, v3, h1, l1);
                Ch[(size_t)z*(MTOT*(D_MODEL/2)) + i0]            = h0;
                Cl[(size_t)z*(MTOT*(D_MODEL/2)) + i0]            = l0;
                Ch[(size_t)z*(MTOT*(D_MODEL/2)) + i0 + 8*(HD/2)] = h1;
                Cl[(size_t)z*(MTOT*(D_MODEL/2)) + i0 + 8*(HD/2)] = l1;
            } else {
                float* C = Cf + (size_t)z * sC;
                *(float2*)&C[(size_t)m*D_MODEL + n]     = make_float2(v0, v1);
                *(float2*)&C[(size_t)(m+8)*D_MODEL + n] = make_float2(v2, v3);
            }
        }
    }
}

// ---------------- Tensor-core flash attention (causal) ------------------------
// Q,K,V as packed bf16 hi/lo [BH][S][HD/2]; O fp32 [B,S,D].
// Br=128 (8 warps x 16 rows), Bc=64. bf16x3 for S=QK^T and O+=PV.
#define FROW 36                         /* uints per smem row (32 data + 4 pad) */
#define FKH  0
#define FKL  (64*FROW)
#define FVH  (128*FROW)
#define FVL  (192*FROW)
#define FQH  0                          /* Q staging reuses same region */
#define FQL  (128*FROW)
#define FLASH_SMEM (256*FROW*4)         /* 36864 B */

__global__ void __launch_bounds__(256) flash_tc(
    const uint32_t* __restrict__ Qh, const uint32_t* __restrict__ Ql,
    const uint32_t* __restrict__ Kh, const uint32_t* __restrict__ Kl,
    const uint32_t* __restrict__ Vh, const uint32_t* __restrict__ Vl,
    float* __restrict__ O)
{
    extern __shared__ uint32_t sm[];
    int tid = threadIdx.x, lane = tid & 31, wid = tid >> 5;
    int qblk = gridDim.x - 1 - blockIdx.x;         // heavy blocks first
    int q0 = qblk * 128;
    int bh = blockIdx.y;
    size_t base = (size_t)bh * SEQ * (HD/2);

    uint32_t smb = (uint32_t)__cvta_generic_to_shared(sm);

    // ---- stage Q (128 x 32 uints, hi+lo), extract persistent fragments ----
    {
        int r = tid >> 1, hs = (tid & 1) * 16;
        const uint4* gh = (const uint4*)(Qh + base + (size_t)(q0 + r)*(HD/2) + hs);
        const uint4* gl = (const uint4*)(Ql + base + (size_t)(q0 + r)*(HD/2) + hs);
        uint4* dh = (uint4*)(sm + FQH + r*FROW + hs);
        uint4* dl = (uint4*)(sm + FQL + r*FROW + hs);
        dh[0]=gh[0]; dh[1]=gh[1]; dh[2]=gh[2]; dh[3]=gh[3];
        dl[0]=gl[0]; dl[1]=gl[1]; dl[2]=gl[2]; dl[3]=gl[3];
    }
    __syncthreads();

    uint32_t qh[4][4], ql[4][4];
    {
        uint32_t qa = smb + (uint32_t)(((wid*16 + (lane & 15))*FROW)*4 + (lane >> 4)*16);
        #pragma unroll
        for (int t = 0; t < 4; t++){
            ldsm_x4(qh[t], qa + FQH*4 + t*32);
            ldsm_x4(ql[t], qa + FQL*4 + t*32);
        }
    }
    __syncthreads();   // done with Q staging; K/V will overwrite

    float o[8][4] = {};
    float mr0 = -INFINITY, mr1 = -INFINITY, l0 = 0.f, l1 = 0.f;
    const float scale = 0.125f;
    int r0g = q0 + wid*16 + (lane >> 2);
    int r1g = r0g + 8;

    int ktiles = 2*qblk + 2;
    for (int t = 0; t < ktiles; t++){
        int k0 = t * 64;
        // ---- load K,V tile (hi+lo): 64 rows x 32 uints each ----
        {
            int r = tid >> 2;
            int c = (tid & 3) * 8;
            size_t gi = base + (size_t)(k0 + r)*(HD/2) + c;
            uint32_t so = r*FROW + c;
            *(uint4*)(sm + FKH + so)     = *(const uint4*)(Kh + gi);
            *(uint4*)(sm + FKH + so + 4) = *(const uint4*)(Kh + gi + 4);
            *(uint4*)(sm + FKL + so)     = *(const uint4*)(Kl + gi);
            *(uint4*)(sm + FKL + so + 4) = *(const uint4*)(Kl + gi + 4);
            *(uint4*)(sm + FVH + so)     = *(const uint4*)(Vh + gi);
            *(uint4*)(sm + FVH + so + 4) = *(const uint4*)(Vh + gi + 4);
            *(uint4*)(sm + FVL + so)     = *(const uint4*)(Vl + gi);
            *(uint4*)(sm + FVL + so + 4) = *(const uint4*)(Vl + gi + 4);
        }
        __syncthreads();

        // ---- S = Q K^T (bf16x3) ----
        float s[8][4] = {};
        #pragma unroll
        for (int t4 = 0; t4 < 4; t4++){
            #pragma unroll
            for (int nb = 0; nb < 4; nb++){
                uint32_t ba = smb + (uint32_t)(((nb*16 + (lane & 15))*FROW)*4 + (lane >> 4)*16 + t4*32);
                uint32_t kh4[4], kl4[4];
                ldsm_x4(kh4, ba + FKH*4);
                ldsm_x4(kl4, ba + FKL*4);
                mma_bf16(s[2*nb],   qh[t4], kh4[0], kh4[2]);
                mma_bf16(s[2*nb],   qh[t4], kl4[0], kl4[2]);
                mma_bf16(s[2*nb],   ql[t4], kh4[0], kh4[2]);
                mma_bf16(s[2*nb+1], qh[t4], kh4[1], kh4[3]);
                mma_bf16(s[2*nb+1], qh[t4], kl4[1], kl4[3]);
                mma_bf16(s[2*nb+1], ql[t4], kh4[1], kh4[3]);
            }
        }

        // ---- scale + causal mask ----
        bool need_mask = (t >= ktiles - 2);
        #pragma unroll
        for (int f = 0; f < 8; f++){
            int colb = k0 + (f>>1)*16 + (f&1)*8 + (lane & 3)*2;
            #pragma unroll
            for (int c = 0; c < 4; c++){
                float v = s[f][c] * scale;
                if (need_mask){
                    int kg = colb + (c & 1);
                    int qg = (c < 2) ? r0g : r1g;
                    if (kg > qg) v = -1e30f;
                }
                s[f][c] = v;
            }
        }

        // ---- online softmax (rows r0g, r1g) ----
        float mx0 = -INFINITY, mx1 = -INFINITY;
        #pragma unroll
        for (int f = 0; f < 8; f++){
            mx0 = fmaxf(mx0, fmaxf(s[f][0], s[f][1]));
            mx1 = fmaxf(mx1, fmaxf(s[f][2], s[f][3]));
        }
        mx0 = fmaxf(mx0, __shfl_xor_sync(0xffffffffu, mx0, 1));
        mx0 = fmaxf(mx0, __shfl_xor_sync(0xffffffffu, mx0, 2));
        mx1 = fmaxf(mx1, __shfl_xor_sync(0xffffffffu, mx1, 1));
        mx1 = fmaxf(mx1, __shfl_xor_sync(0xffffffffu, mx1, 2));
        float mn0 = fmaxf(mr0, mx0), mn1 = fmaxf(mr1, mx1);
        float a0 = __expf(mr0 - mn0), a1 = __expf(mr1 - mn1);
        mr0 = mn0; mr1 = mn1;
        float ps0 = 0.f, ps1 = 0.f;
        #pragma unroll
        for (int f = 0; f < 8; f++){
            s[f][0] = __expf(s[f][0] - mn0);
            s[f][1] = __expf(s[f][1] - mn0);
            s[f][2] = __expf(s[f][2] - mn1);
            s[f][3] = __expf(s[f][3] - mn1);
            ps0 += s[f][0] + s[f][1];
            ps1 += s[f][2] + s[f][3];
        }
        ps0 += __shfl_xor_sync(0xffffffffu, ps0, 1);
        ps0 += __shfl_xor_sync(0xffffffffu, ps0, 2);
        ps1 += __shfl_xor_sync(0xffffffffu, ps1, 1);
        ps1 += __shfl_xor_sync(0xffffffffu, ps1, 2);
        l0 = l0 * a0 + ps0;
        l1 = l1 * a1 + ps1;
        #pragma unroll
        for (int f = 0; f < 8; f++){
            o[f][0] *= a0; o[f][1] *= a0;
            o[f][2] *= a1; o[f][3] *= a1;
        }

        // ---- P fragments (in-register split to bf16 hi/lo) ----
        uint32_t ph[4][4], pl[4][4];
        #pragma unroll
        for (int t4 = 0; t4 < 4; t4++){
            split2(s[2*t4][0],   s[2*t4][1],   ph[t4][0], pl[t4][0]);
            split2(s[2*t4][2],   s[2*t4][3],   ph[t4][1], pl[t4][1]);
            split2(s[2*t4+1][0], s[2*t4+1][1], ph[t4][2], pl[t4][2]);
            split2(s[2*t4+1][2], s[2*t4+1][3], ph[t4][3], pl[t4][3]);
        }

        // ---- O += P V (bf16x3), V via ldmatrix.trans ----
        #pragma unroll
        for (int t4 = 0; t4 < 4; t4++){
            #pragma unroll
            for (int nb = 0; nb < 4; nb++){
                uint32_t va = smb + (uint32_t)(((t4*16 + (lane & 15))*FROW)*4 + (lane >> 4)*16 + nb*32);
                uint32_t vh4[4], vl4[4];
                ldsm_x4t(vh4, va + FVH*4);
                ldsm_x4t(vl4, va + FVL*4);
                mma_bf16(o[2*nb],   ph[t4], vh4[0], vh4[1]);
                mma_bf16(o[2*nb],   ph[t4], vl4[0], vl4[1]);
                mma_bf16(o[2*nb],   pl[t4], vh4[0], vh4[1]);
                mma_bf16(o[2*nb+1], ph[t4], vh4[2], vh4[3]);
                mma_bf16(o[2*nb+1], ph[t4], vl4[2], vl4[3]);
                mma_bf16(o[2*nb+1], pl[t4], vh4[2], vh4[3]);
            }
        }
        __syncthreads();   // all smem reads done before next tile load
    }

    // ---- epilogue: normalize, write [B,S,D] fp32 ----
    int b = bh >> 3, h = bh & 7;
    float inv0 = 1.0f / l0, inv1 = 1.0f / l1;
    #pragma unroll
    for (int f = 0; f < 8; f++){
        int col = h*HD + (f>>1)*16 + (f&1)*8 + (lane & 3)*2;
        *(float2*)&O[(size_t)(b*SEQ + r0g)*D_MODEL + col] =
            make_float2(o[f][0]*inv0, o[f][1]*inv0);
        *(float2*)&O[(size_t)(b*SEQ + r1g)*D_MODEL + col] =
            make_float2(o[f][2]*inv1, o[f][3]*inv1);
    }
}

// ---------------- launch ------------------------------------------------------
extern "C" void kernel_launch(void* const* d_in, const int* in_sizes, int n_in,
                              void* d_out, int out_size) {
    const float* x   = (const float*)d_in[0];
    const float* Wq  = (const float*)d_in[1];
    const float* Wk  = (const float*)d_in[2];
    const float* Wv  = (const float*)d_in[3];
    const float* R   = (const float*)d_in[4];
    const float* ipw = (const float*)d_in[5];
    const float* ipb = (const float*)d_in[6];
    const float* ow  = (const float*)d_in[7];
    const float* ob  = (const float*)d_in[8];
    float* out = (float*)d_out;

    float *qkv, *attn, *tab;
    uint32_t *hh, *hl;
    cudaGetSymbolAddress((void**)&qkv,  g_qkv);
    cudaGetSymbolAddress((void**)&hh,   g_hh);
    cudaGetSymbolAddress((void**)&hl,   g_hl);
    cudaGetSymbolAddress((void**)&attn, g_attn);
    cudaGetSymbolAddress((void**)&tab,  g_tab);

    static int inited = 0;
    if (!inited) {
        cudaFuncSetAttribute(gemm_tc<0>, cudaFuncAttributeMaxDynamicSharedMemorySize, GEMM_SMEM);
        cudaFuncSetAttribute(gemm_tc<1>, cudaFuncAttributeMaxDynamicSharedMemorySize, GEMM_SMEM);
        cudaFuncSetAttribute(gemm_tc<2>, cudaFuncAttributeMaxDynamicSharedMemorySize, GEMM_SMEM);
        cudaFuncSetAttribute(flash_tc,   cudaFuncAttributeMaxDynamicSharedMemorySize, FLASH_SMEM);
        inited = 1;
    }

    const long MD  = (long)MTOT * D_MODEL;
    const long WW  = (long)D_MODEL * D_MODEL;
    const long HDP = (long)MTOT * (D_MODEL/2);   // uints per heads tensor

    // 1) cos/sin table
    rope_table_kernel<<<SEQ, 256>>>(R, tab);

    // 2) q,k,v = x @ W^T with fused RoPE (fp32 out)
    dim3 gq(D_MODEL/128, MTOT/128, 1);
    gemm_tc<2><<<gq, 256, GEMM_SMEM>>>(x, 0, Wq, 0, nullptr, 0, qkv,        nullptr, nullptr, 0, tab);
    gemm_tc<2><<<gq, 256, GEMM_SMEM>>>(x, 0, Wk, 0, nullptr, 0, qkv + MD,   nullptr, nullptr, 0, tab);
    gemm_tc<2><<<gq, 256, GEMM_SMEM>>>(x, 0, Wv, 0, nullptr, 0, qkv + 2*MD, nullptr, nullptr, 0, tab);

    // 3) in_proj: bias + head-permute + bf16 hi/lo pack, z-batched
    dim3 gi(D_MODEL/128, MTOT/128, 3);
    gemm_tc<1><<<gi, 256, GEMM_SMEM>>>(qkv, MD, ipw, WW, ipb, D_MODEL,
                                       nullptr, hh, hl, 0, nullptr);

    // 4) causal flash attention (tensor cores)
    flash_tc<<<dim3(SEQ/128, BH), 256, FLASH_SMEM>>>(
        hh, hl, hh + HDP, hl + HDP, hh + 2*HDP, hl + 2*HDP, attn);

    // 5) output projection
    dim3 go(D_MODEL/128, MTOT/128, 1);
    gemm_tc<0><<<go, 256, GEMM_SMEM>>>(attn, 0, ow, 0, ob, 0, out, nullptr, nullptr, 0, nullptr);
}